// round 16
// baseline (speedup 1.0000x reference)
#include <cuda_runtime.h>
#include <cuda_bf16.h>

// GRU scan: B=2048 sequences, T=2048 steps, D=3 input, H=32 hidden.
// out[b, t] = h[0] after step t.
//
// R16 = R8's occupancy (2 batches/warp, 1024 warps, 256x128 grid, occ-2)
// restructured for register pressure + in-warp overlap:
//  - weights k-pair packed f32x2 and SHARED by both batches (48 u64 = 96
//    regs, no duplication; R8 duplicated into 192). True demand ~155 clean.
//  - per-batch matvec (48 fma2 each) with separate accumulators; order
//    matvecA, matvecB, actA, actB so each batch's fold/activation latency
//    is hidden under the other batch's matvec (in-warp pipelining).
//  - accumulators seeded with the input gate in the lo half (fold -> full
//    pre-activation, no extra adds).
//  - r/z share one RCP (iq = rcp(dr*dz)); 10 MUFU/warp-step vs 12.
//  - double-buffered smem h slabs, one syncwarp/step; t-loop unrolled x2.
//  - EX2/RCP activations (tanh.approx = fma-pipe polyfill on sm_103a).
// occ-4 1-batch path abandoned: R11/R12/R15 all hit the 128-reg cap
// (ptxas fills the budget); clean 2-warp config is the operating point.

#define T_DIM 2048
#define B_DIM 2048

typedef unsigned long long u64;

__device__ __forceinline__ u64 fma2(u64 a, u64 b, u64 c) {
    u64 d;
    asm("fma.rn.f32x2 %0, %1, %2, %3;" : "=l"(d) : "l"(a), "l"(b), "l"(c));
    return d;
}

__device__ __forceinline__ u64 pack2(float a, float b) {
    u64 d;
    asm("mov.b64 %0, {%1, %2};" : "=l"(d) : "f"(a), "f"(b));
    return d;
}

__device__ __forceinline__ float foldadd(u64 p) {
    float lo, hi;
    asm("mov.b64 {%0, %1}, %2;" : "=f"(lo), "=f"(hi) : "l"(p));
    return lo + hi;
}

__device__ __forceinline__ float rcp_fast(float x) {
    float y;
    asm("rcp.approx.f32 %0, %1;" : "=f"(y) : "f"(x));
    return y;
}

__device__ __forceinline__ float exp_fast(float x) {
    // e^x = 2^(x*log2e); EX2 on MUFU
    float y;
    asm("ex2.approx.f32 %0, %1;" : "=f"(y) : "f"(x * 1.4426950408889634f));
    return y;
}

struct BatchState {
    float h;
    float x0, x1, x2;
};

__global__ void __launch_bounds__(128, 2)
gru_scan_kernel(const float* __restrict__ inp,      // [B, T, 3]
                const float* __restrict__ wih,      // [96, 3]
                const float* __restrict__ whh,      // [96, 32]
                const float* __restrict__ bias,     // [96]
                const float* __restrict__ bias_n,   // [32]
                float* __restrict__ out)            // [B, T]
{
    const int lane = threadIdx.x & 31;
    const int warp = threadIdx.x >> 5;
    const int b0   = (blockIdx.x * 4 + warp) * 2;   // batches b0, b0+1

    // per-warp double-buffered h slabs, per batch; 16B-aligned for LDS.128
    __shared__ __align__(16) float hb[4][2][2][32];  // [warp][slot][batch][unit]

    // --- Whh rows for this lane as packed k-pairs, SHARED by both batches ---
    u64 wr[16], wz[16], wa[16];
    {
        const u64* r0 = reinterpret_cast<const u64*>(whh + (size_t)(lane) * 32);
        const u64* r1 = reinterpret_cast<const u64*>(whh + (size_t)(32 + lane) * 32);
        const u64* r2 = reinterpret_cast<const u64*>(whh + (size_t)(64 + lane) * 32);
#pragma unroll
        for (int i = 0; i < 16; ++i) { wr[i] = r0[i]; wz[i] = r1[i]; wa[i] = r2[i]; }
    }
    const float wir0 = wih[lane * 3 + 0], wir1 = wih[lane * 3 + 1], wir2 = wih[lane * 3 + 2];
    const float wiz0 = wih[(32 + lane) * 3 + 0], wiz1 = wih[(32 + lane) * 3 + 1], wiz2 = wih[(32 + lane) * 3 + 2];
    const float wia0 = wih[(64 + lane) * 3 + 0], wia1 = wih[(64 + lane) * 3 + 1], wia2 = wih[(64 + lane) * 3 + 2];
    const float bir = bias[lane], biz = bias[32 + lane];
    const float bia = bias[64 + lane] + bias_n[lane];   // bias_n folded

    const float* xp = inp + (size_t)b0 * T_DIM * 3;
    float*       op = out + (size_t)b0 * T_DIM;

    BatchState A, Bst;
    A.h = 0.0f; Bst.h = 0.0f;
    A.x0 = __ldg(xp + 0);             A.x1 = __ldg(xp + 1);             A.x2 = __ldg(xp + 2);
    Bst.x0 = __ldg(xp + T_DIM * 3 + 0); Bst.x1 = __ldg(xp + T_DIM * 3 + 1); Bst.x2 = __ldg(xp + T_DIM * 3 + 2);

#pragma unroll 2
    for (int t = 0; t < T_DIM; ++t) {
        const int slot = t & 1;

        // input gates (scalar, shared weight regs)
        float irA = fmaf(wir2, A.x2, fmaf(wir1, A.x1, fmaf(wir0, A.x0, bir)));
        float izA = fmaf(wiz2, A.x2, fmaf(wiz1, A.x1, fmaf(wiz0, A.x0, biz)));
        float iaA = fmaf(wia2, A.x2, fmaf(wia1, A.x1, fmaf(wia0, A.x0, bia)));
        float irB = fmaf(wir2, Bst.x2, fmaf(wir1, Bst.x1, fmaf(wir0, Bst.x0, bir)));
        float izB = fmaf(wiz2, Bst.x2, fmaf(wiz1, Bst.x1, fmaf(wiz0, Bst.x0, biz)));
        float iaB = fmaf(wia2, Bst.x2, fmaf(wia1, Bst.x1, fmaf(wia0, Bst.x0, bia)));
        {   // prefetch next x (clamped)
            int tn = (t + 1 < T_DIM) ? (t + 1) : t;
            const float* nx = xp + (size_t)tn * 3;
            A.x0 = __ldg(nx + 0);               A.x1 = __ldg(nx + 1);               A.x2 = __ldg(nx + 2);
            Bst.x0 = __ldg(nx + T_DIM * 3 + 0); Bst.x1 = __ldg(nx + T_DIM * 3 + 1); Bst.x2 = __ldg(nx + T_DIM * 3 + 2);
        }

        // publish both h's; double-buffered slot => one syncwarp per step
        hb[warp][slot][0][lane] = A.h;
        hb[warp][slot][1][lane] = Bst.h;
        __syncwarp();

        const ulonglong2* hpA = reinterpret_cast<const ulonglong2*>(&hb[warp][slot][0][0]);
        const ulonglong2* hpB = reinterpret_cast<const ulonglong2*>(&hb[warp][slot][1][0]);

        // ---- matvec A (k-pair packed, ig-seeded accumulators) ----
        u64 arA = pack2(irA, 0.0f), azA = pack2(izA, 0.0f), aaA = pack2(iaA, 0.0f);
#pragma unroll
        for (int i = 0; i < 8; ++i) {
            ulonglong2 hv = hpA[i];          // broadcast: hA[4i..4i+3]
            arA = fma2(wr[2 * i],     hv.x, arA);
            azA = fma2(wz[2 * i],     hv.x, azA);
            aaA = fma2(wa[2 * i],     hv.x, aaA);
            arA = fma2(wr[2 * i + 1], hv.y, arA);
            azA = fma2(wz[2 * i + 1], hv.y, azA);
            aaA = fma2(wa[2 * i + 1], hv.y, aaA);
        }

        // ---- matvec B (independent chain; overlaps A's fold/activation) ----
        u64 arB = pack2(irB, 0.0f), azB = pack2(izB, 0.0f), aaB = pack2(iaB, 0.0f);
#pragma unroll
        for (int i = 0; i < 8; ++i) {
            ulonglong2 hv = hpB[i];
            arB = fma2(wr[2 * i],     hv.x, arB);
            azB = fma2(wz[2 * i],     hv.x, azB);
            aaB = fma2(wa[2 * i],     hv.x, aaB);
            arB = fma2(wr[2 * i + 1], hv.y, arB);
            azB = fma2(wz[2 * i + 1], hv.y, azB);
            aaB = fma2(wa[2 * i + 1], hv.y, aaB);
        }

        // ---- activation A ----
        {
            float rs = foldadd(arA), zs = foldadd(azA), as_ = foldadd(aaA);
            float dr = 1.0f + exp_fast(-rs);
            float dz = 1.0f + exp_fast(-zs);
            float iq = rcp_fast(dr * dz);        // shared RCP for r and z
            float r  = iq * dz;
            float z  = iq * dr;
            float narg = fmaf(r, as_ - iaA, iaA);        // ia + r*ha
            float dn = exp_fast(2.0f * narg) + 1.0f;
            float n  = 1.0f - 2.0f * rcp_fast(dn);
            A.h = fmaf(z, A.h - n, n);           // (1-z)*n + z*h
        }

        // ---- activation B ----
        {
            float rs = foldadd(arB), zs = foldadd(azB), as_ = foldadd(aaB);
            float dr = 1.0f + exp_fast(-rs);
            float dz = 1.0f + exp_fast(-zs);
            float iq = rcp_fast(dr * dz);
            float r  = iq * dz;
            float z  = iq * dr;
            float narg = fmaf(r, as_ - iaB, iaB);
            float dn = exp_fast(2.0f * narg) + 1.0f;
            float n  = 1.0f - 2.0f * rcp_fast(dn);
            Bst.h = fmaf(z, Bst.h - n, n);
        }

        if (lane == 0) {
            op[t]         = A.h;
            op[T_DIM + t] = Bst.h;
        }
    }
}

extern "C" void kernel_launch(void* const* d_in, const int* in_sizes, int n_in,
                              void* d_out, int out_size) {
    const float* inp    = (const float*)d_in[0];
    const float* wih    = (const float*)d_in[1];
    const float* whh    = (const float*)d_in[2];
    const float* bias   = (const float*)d_in[3];
    const float* bias_n = (const float*)d_in[4];
    float* out = (float*)d_out;

    // 2 batches per warp, 4 warps per CTA -> 256 CTAs, 1024 warps.
    gru_scan_kernel<<<B_DIM / 8, 128>>>(inp, wih, whh, bias, bias_n, out);
}